// round 5
// baseline (speedup 1.0000x reference)
#include <cuda_runtime.h>
#include <math.h>

typedef unsigned long long ull;

constexpr int B  = 128;
constexpr int S  = 256;
constexpr int T  = 256;
constexpr int V  = 512;
constexpr int E  = 256;
constexpr int H  = 512;
constexpr int G  = 4 * H;     // 2048
constexpr int H2 = 2 * H;     // 1024
constexpr int NB = 128;       // persistent grid size (<= SM count)
constexpr int NT = 256;       // threads per CTA

// ---------------- device scratch ----------------
__device__ __align__(256) float g_xs  [(size_t)2 * S * B * E];
__device__ __align__(256) float g_pre [(size_t)2 * S * B * G];
__device__ __align__(256) float g_y0  [(size_t)2 * S * B * H2];
__device__ __align__(256) float g_enc [(size_t)S * B * H2];
__device__ __align__(256) float g_edec[(size_t)T * B * E];
__device__ __align__(256) float g_h   [2 * B * H];
__device__ __align__(256) float g_c   [2 * B * H];
__device__ __align__(256) float g_gates[2 * B * G];
__device__ __align__(256) float g_q   [B * H2];
__device__ __align__(256) float g_ctx [B * H2];
__device__ __align__(256) float g_d0h [B * H];
__device__ __align__(256) float g_d0c [B * H];
__device__ __align__(256) float g_d1h [B * H];
__device__ __align__(256) float g_d1c [B * H];

__device__ unsigned g_cnt;   // barrier arrival counter (returns to 0 after each barrier)
__device__ unsigned g_flag;  // monotonic release flag (persists across launches/replays)

// ---------------- grid-wide barrier (all NB CTAs must participate) ----------------
__device__ __forceinline__ void gbar(unsigned& phase)
{
    __syncthreads();
    if (threadIdx.x == 0) {
        __threadfence();                       // publish this CTA's writes
        const unsigned target = phase + 1;
        if (atomicAdd(&g_cnt, 1) == NB - 1) {
            g_cnt = 0;
            __threadfence();
            atomicExch(&g_flag, target);       // release
        } else {
            while (*(volatile unsigned*)&g_flag < target) { __nanosleep(32); }
            __threadfence();
        }
        phase = target;
    }
    __syncthreads();
}

// ---------------- packed fp32 helpers ----------------
union UPair { ull u; float2 f; };

__device__ __forceinline__ ull dupf(float x)
{
    ull r;
    asm("mov.b64 %0, {%1, %1};" : "=l"(r) : "f"(x));
    return r;
}

#define FMA2(d, a, b) asm("fma.rn.f32x2 %0, %1, %2, %0;" : "+l"(d) : "l"(a), "l"(b))

__device__ __forceinline__ float sigf(float x) { return 1.f / (1.f + expf(-x)); }

// ---------------- GEMM tile core (TM x TN, 256 threads, f32x2 accumulation) ----------------
// C_tile(TM x TN) += A(TM rows, lda) @ W(TN rows, ldw)^T over K.
// acc[rp][j]: packed pair {row ty4+2rp, row ty4+2rp+1} for column tx4+j.
template<int TM, int TN, bool ACG>
__device__ __forceinline__ void gcore(
    const float* __restrict__ A, int lda,
    const float* __restrict__ W, int ldw,
    int K, float (*As)[130], ull (*Bs)[66], ull acc[2][4])
{
    const int tid = threadIdx.x;
    const int tx4 = (tid % (TN / 4)) * 4;
    const int ty4 = (tid / (TN / 4)) * 4;

    int arow, ak;
    if (TM == 64) { arow = tid >> 2; ak = (tid & 3) * 4; }
    else          { arow = tid >> 1; ak = (tid & 1) * 8; }
    const bool wact = tid < TN * 4;
    const int wrow = tid >> 2;
    const int wk = (tid & 3) * 4;

    const float* ap = A + (size_t)arow * lda + ak;
    const float* wp = W + (size_t)(wact ? wrow : 0) * ldw + wk;

    #pragma unroll 1
    for (int kk = 0; kk < K; kk += 16) {
        float4 a0, a1, wv;
        a0 = ACG ? __ldcg((const float4*)(ap + kk)) : *(const float4*)(ap + kk);
        if (TM == 128)
            a1 = ACG ? __ldcg((const float4*)(ap + kk + 4)) : *(const float4*)(ap + kk + 4);
        if (wact) wv = *(const float4*)(wp + kk);
        __syncthreads();
        As[ak + 0][arow] = a0.x; As[ak + 1][arow] = a0.y;
        As[ak + 2][arow] = a0.z; As[ak + 3][arow] = a0.w;
        if (TM == 128) {
            As[ak + 4][arow] = a1.x; As[ak + 5][arow] = a1.y;
            As[ak + 6][arow] = a1.z; As[ak + 7][arow] = a1.w;
        }
        if (wact) {
            Bs[wk + 0][wrow] = dupf(wv.x); Bs[wk + 1][wrow] = dupf(wv.y);
            Bs[wk + 2][wrow] = dupf(wv.z); Bs[wk + 3][wrow] = dupf(wv.w);
        }
        __syncthreads();
        #pragma unroll
        for (int k = 0; k < 16; ++k) {
            const ull a01 = *(const ull*)&As[k][ty4];
            const ull a23 = *(const ull*)&As[k][ty4 + 2];
            const ulonglong2 b01 = *(const ulonglong2*)&Bs[k][tx4];
            const ulonglong2 b23 = *(const ulonglong2*)&Bs[k][tx4 + 2];
            FMA2(acc[0][0], a01, b01.x); FMA2(acc[0][1], a01, b01.y);
            FMA2(acc[0][2], a01, b23.x); FMA2(acc[0][3], a01, b23.y);
            FMA2(acc[1][0], a23, b01.x); FMA2(acc[1][1], a23, b01.y);
            FMA2(acc[1][2], a23, b23.x); FMA2(acc[1][3], a23, b23.y);
        }
    }
}

template<int TN>
__device__ __forceinline__ void store_tile(
    ull acc[2][4],
    const float* __restrict__ Cin, int ldcin,
    const float* __restrict__ b0, const float* __restrict__ b1,
    float* __restrict__ C, int ldc)
{
    const int tid = threadIdx.x;
    const int tx4 = (tid % (TN / 4)) * 4;
    const int ty4 = (tid / (TN / 4)) * 4;
    float bb[4] = {0.f, 0.f, 0.f, 0.f};
    if (b0) {
        #pragma unroll
        for (int j = 0; j < 4; ++j) bb[j] += b0[tx4 + j];
    }
    if (b1) {
        #pragma unroll
        for (int j = 0; j < 4; ++j) bb[j] += b1[tx4 + j];
    }
    #pragma unroll
    for (int rp = 0; rp < 2; ++rp) {
        #pragma unroll
        for (int hh = 0; hh < 2; ++hh) {
            const int row = ty4 + rp * 2 + hh;
            #pragma unroll
            for (int j = 0; j < 4; ++j) {
                UPair u; u.u = acc[rp][j];
                float v = hh ? u.f.y : u.f.x;
                v += bb[j];
                if (Cin) v += Cin[(size_t)row * ldcin + tx4 + j];
                C[(size_t)row * ldc + tx4 + j] = v;
            }
        }
    }
}

// ---------------- big precompute GEMM (one source, z-batched) ----------------
__global__ __launch_bounds__(256) void gemm2_k(
    const float* __restrict__ A, int lda, int K,
    const float* __restrict__ W, int ldw,
    const float* __restrict__ b0, const float* __restrict__ b1,
    float* __restrict__ C, int ldc,
    long long zsA, long long zsW, long long zsB, long long zsC)
{
    __shared__ __align__(16) float As[16][130];
    __shared__ __align__(16) ull   Bs[16][66];
    const int z = blockIdx.z;
    A += z * zsA; W += z * zsW; C += z * zsC;
    // NOTE: bias pointers must carry the N-tile offset (blockIdx.x*64) because
    // store_tile indexes bias tile-relative. (This was the round-2 bug.)
    const float* bb0 = b0 ? b0 + z * zsB + (size_t)blockIdx.x * 64 : nullptr;
    const float* bb1 = b1 ? b1 + z * zsB + (size_t)blockIdx.x * 64 : nullptr;
    ull acc[2][4] = {{0, 0, 0, 0}, {0, 0, 0, 0}};
    gcore<64, 64, false>(A + (size_t)blockIdx.y * 64 * lda, lda,
                         W + (size_t)blockIdx.x * 64 * ldw, ldw, K, As, Bs, acc);
    store_tile<64>(acc, nullptr, 0, bb0, bb1,
                   C + (size_t)blockIdx.y * 64 * ldc + blockIdx.x * 64, ldc);
}

// ---------------- embedding ----------------
__global__ void embed_src_k(const int* __restrict__ src, const float* __restrict__ emb)
{
    const long long i = (long long)blockIdx.x * 256 + threadIdx.x;
    if (i >= (long long)S * B * E) return;
    const int j = (int)(i % E);
    const long long r = i / E;
    const int b = (int)(r % B);
    const int t = (int)(r / B);
    const int tok = src[b * S + t];
    const float v = (tok == 0) ? 0.f : emb[(size_t)tok * E + j];
    g_xs[((size_t)t * B + b) * E + j] = v;
    g_xs[(size_t)S * B * E + ((size_t)(S - 1 - t) * B + b) * E + j] = v;
}

__global__ void embed_dec_k(const int* __restrict__ dec, const float* __restrict__ emb)
{
    const long long i = (long long)blockIdx.x * 256 + threadIdx.x;
    if (i >= (long long)T * B * E) return;
    const int j = (int)(i % E);
    const long long r = i / E;
    const int b = (int)(r % B);
    const int t = (int)(r / B);
    const int tok = dec[b * T + t];
    g_edec[((size_t)t * B + b) * E + j] = (tok == 0) ? 0.f : emb[(size_t)tok * E + j];
}

// ---------------- persistent encoder layer (both dirs, all 256 steps) ----------------
__global__ __launch_bounds__(256) void enc_layer_k(
    const float* __restrict__ pre,   // [2][S][B][G]
    const float* __restrict__ Whh,   // [2][G][H]
    float* __restrict__ ynorm,       // [S][B][H2]
    float* __restrict__ yrev,        // [S][B][H2] (reversed) or null
    float* __restrict__ dsth, float* __restrict__ dstc)
{
    __shared__ __align__(16) float As[16][130];
    __shared__ __align__(16) ull   Bs[16][66];
    const int cta = blockIdx.x, tid = threadIdx.x;
    unsigned phase = *(volatile unsigned*)&g_flag;

    for (int i = cta * NT + tid; i < 2 * B * H; i += NB * NT) { g_h[i] = 0.f; g_c[i] = 0.f; }
    gbar(phase);

    const int dir = cta >> 6, rr = cta & 63, mt = rr >> 5, nt = rr & 31;
    const float* Atile = g_h + (size_t)dir * B * H + (size_t)mt * 64 * H;
    const float* Wtile = Whh + (size_t)dir * G * H + (size_t)nt * 64 * H;
    const float* preD  = pre + (size_t)dir * S * B * G + (size_t)mt * 64 * G + nt * 64;
    float* gout = g_gates + (size_t)dir * B * G + (size_t)mt * 64 * G + nt * 64;

    #pragma unroll 1
    for (int s = 0; s < S; ++s) {
        ull acc[2][4] = {{0, 0, 0, 0}, {0, 0, 0, 0}};
        gcore<64, 64, true>(Atile, H, Wtile, H, H, As, Bs, acc);
        store_tile<64>(acc, preD + (size_t)s * B * G, G, nullptr, nullptr, gout, G);
        gbar(phase);
        #pragma unroll 1
        for (int i = cta * NT + tid; i < 2 * B * H; i += NB * NT) {
            const int d = i >> 16;            // B*H = 65536
            const int r2 = i & (B * H - 1);
            const int b = r2 >> 9, j = r2 & 511;
            const float* gp = g_gates + (size_t)d * B * G + (size_t)b * G;
            const float gi = __ldcg(gp + j);
            const float gf = __ldcg(gp + H + j);
            const float gg = __ldcg(gp + 2 * H + j);
            const float go = __ldcg(gp + 3 * H + j);
            const float cn = sigf(gf) * g_c[i] + sigf(gi) * tanhf(gg);
            const float hn = sigf(go) * tanhf(cn);
            g_c[i] = cn; g_h[i] = hn;
            const int tt = d ? (S - 1 - s) : s;
            ynorm[(size_t)tt * B * H2 + (size_t)b * H2 + d * H + j] = hn;
            if (yrev)
                yrev[(size_t)(S - 1 - tt) * B * H2 + (size_t)b * H2 + d * H + j] = hn;
        }
        gbar(phase);
    }
    for (int i = cta * NT + tid; i < B * H; i += NB * NT) {
        dsth[i] = __ldcg(&g_h[i]) + __ldcg(&g_h[B * H + i]);
        dstc[i] = __ldcg(&g_c[i]) + __ldcg(&g_c[B * H + i]);
    }
}

// ---------------- persistent decoder (all 256 steps) ----------------
__global__ __launch_bounds__(256) void dec_k(
    const float* __restrict__ pre,    // [T][B][G]  (emb part + both biases)
    const float* __restrict__ Wc,     // dWih0 + E  (ctx columns), ldw = E+H2
    int ldwc,
    const float* __restrict__ dWhh0,
    const float* __restrict__ dWih1,  const float* __restrict__ dWhh1,
    const float* __restrict__ dbih1,  const float* __restrict__ dbhh1,
    const float* __restrict__ Wq,     const float* __restrict__ bq,
    const float* __restrict__ Wout,   const float* __restrict__ bout,
    const int*   __restrict__ src,
    const float* __restrict__ enc,
    float* __restrict__ out)
{
    __shared__ __align__(16) float As[16][130];
    __shared__ __align__(16) ull   Bs[16][66];
    __shared__ float qs[H2];
    __shared__ float sc[S];
    __shared__ float red[8];
    __shared__ float s_max, s_sum;

    const int cta = blockIdx.x, tid = threadIdx.x;
    const int lane = tid & 31, w = tid >> 5;
    unsigned phase = *(volatile unsigned*)&g_flag;

    #pragma unroll 1
    for (int t = 0; t < T; ++t) {
        // ---- P1: q = d1h @ Wq^T + bq  (CTAs 0..31), logits(t-1) (CTAs 32..47)
        if (cta < 32) {
            ull acc[2][4] = {{0, 0, 0, 0}, {0, 0, 0, 0}};
            gcore<128, 32, true>(g_d1h, H, Wq + (size_t)cta * 32 * H, H, H, As, Bs, acc);
            store_tile<32>(acc, nullptr, 0, bq + cta * 32, nullptr, g_q + cta * 32, H2);
        } else if (cta < 48 && t > 0) {
            const int nt = cta - 32;
            ull acc[2][4] = {{0, 0, 0, 0}, {0, 0, 0, 0}};
            gcore<128, 32, true>(g_d1h, H, Wout + (size_t)nt * 32 * H, H, H, As, Bs, acc);
            store_tile<32>(acc, nullptr, 0, bout + nt * 32, nullptr,
                           out + (size_t)(t - 1) * V + nt * 32, T * V);
        }
        gbar(phase);

        // ---- P2: attention (CTA = batch)
        {
            const int b = cta;
            for (int k = tid * 4; k < H2; k += NT * 4)
                *(float4*)&qs[k] = __ldcg((const float4*)(g_q + (size_t)b * H2 + k));
            __syncthreads();
            for (int s = w; s < S; s += 8) {
                const float* eb = enc + ((size_t)s * B + b) * H2;
                float sum = 0.f;
                #pragma unroll
                for (int k = lane * 4; k < H2; k += 128) {
                    const float4 e = *(const float4*)(eb + k);
                    sum += e.x * qs[k] + e.y * qs[k + 1] + e.z * qs[k + 2] + e.w * qs[k + 3];
                }
                #pragma unroll
                for (int o = 16; o; o >>= 1) sum += __shfl_xor_sync(0xffffffffu, sum, o);
                if (lane == 0) sc[s] = (src[b * S + s] != 0) ? sum : -1e9f;
            }
            __syncthreads();
            const float v = sc[tid];
            float m = v;
            #pragma unroll
            for (int o = 16; o; o >>= 1) m = fmaxf(m, __shfl_xor_sync(0xffffffffu, m, o));
            if (lane == 0) red[w] = m;
            __syncthreads();
            if (tid == 0) {
                float mm = red[0];
                #pragma unroll
                for (int i = 1; i < 8; ++i) mm = fmaxf(mm, red[i]);
                s_max = mm;
            }
            __syncthreads();
            const float ev = expf(v - s_max);
            float sum = ev;
            #pragma unroll
            for (int o = 16; o; o >>= 1) sum += __shfl_xor_sync(0xffffffffu, sum, o);
            if (lane == 0) red[w] = sum;
            __syncthreads();
            if (tid == 0) {
                float ss = 0.f;
                #pragma unroll
                for (int i = 0; i < 8; ++i) ss += red[i];
                s_sum = ss;
            }
            __syncthreads();
            sc[tid] = ev / s_sum;
            __syncthreads();
            const int k4 = tid * 4;
            float4 a = {0.f, 0.f, 0.f, 0.f};
            const float* ep = enc + (size_t)b * H2 + k4;
            #pragma unroll 4
            for (int s = 0; s < S; ++s) {
                const float p = sc[s];
                const float4 e = *(const float4*)(ep + (size_t)s * B * H2);
                a.x += p * e.x; a.y += p * e.y; a.z += p * e.z; a.w += p * e.w;
            }
            *(float4*)(g_ctx + (size_t)b * H2 + k4) = a;
        }
        gbar(phase);

        // ---- P3: cell0 gates (K-split over 2 partials)
        {
            const int kh = cta >> 6, nt = cta & 63;
            ull acc[2][4] = {{0, 0, 0, 0}, {0, 0, 0, 0}};
            if (kh == 0) {
                gcore<128, 32, true>(g_ctx, H2, Wc + (size_t)nt * 32 * ldwc, ldwc, H2, As, Bs, acc);
                store_tile<32>(acc, nullptr, 0, nullptr, nullptr, g_gates + nt * 32, G);
            } else {
                gcore<128, 32, true>(g_d0h, H, dWhh0 + (size_t)nt * 32 * H, H, H, As, Bs, acc);
                store_tile<32>(acc, pre + (size_t)t * B * G + nt * 32, G, nullptr, nullptr,
                               g_gates + (size_t)B * G + nt * 32, G);
            }
        }
        gbar(phase);

        // ---- P4: cell0 pointwise
        for (int i = cta * NT + tid; i < B * H; i += NB * NT) {
            const int b = i >> 9, j = i & 511;
            const float* p0 = g_gates + (size_t)b * G;
            const float* p1 = p0 + (size_t)B * G;
            const float gi = __ldcg(p0 + j)         + __ldcg(p1 + j);
            const float gf = __ldcg(p0 + H + j)     + __ldcg(p1 + H + j);
            const float gg = __ldcg(p0 + 2 * H + j) + __ldcg(p1 + 2 * H + j);
            const float go = __ldcg(p0 + 3 * H + j) + __ldcg(p1 + 3 * H + j);
            const float cn = sigf(gf) * g_d0c[i] + sigf(gi) * tanhf(gg);
            g_d0c[i] = cn;
            g_d0h[i] = sigf(go) * tanhf(cn);
        }
        gbar(phase);

        // ---- P5: cell1 gates (K-split)
        {
            const int kh = cta >> 6, nt = cta & 63;
            ull acc[2][4] = {{0, 0, 0, 0}, {0, 0, 0, 0}};
            if (kh == 0) {
                gcore<128, 32, true>(g_d0h, H, dWih1 + (size_t)nt * 32 * H, H, H, As, Bs, acc);
                store_tile<32>(acc, nullptr, 0, dbih1 + nt * 32, dbhh1 + nt * 32,
                               g_gates + nt * 32, G);
            } else {
                gcore<128, 32, true>(g_d1h, H, dWhh1 + (size_t)nt * 32 * H, H, H, As, Bs, acc);
                store_tile<32>(acc, nullptr, 0, nullptr, nullptr,
                               g_gates + (size_t)B * G + nt * 32, G);
            }
        }
        gbar(phase);

        // ---- P6: cell1 pointwise
        for (int i = cta * NT + tid; i < B * H; i += NB * NT) {
            const int b = i >> 9, j = i & 511;
            const float* p0 = g_gates + (size_t)b * G;
            const float* p1 = p0 + (size_t)B * G;
            const float gi = __ldcg(p0 + j)         + __ldcg(p1 + j);
            const float gf = __ldcg(p0 + H + j)     + __ldcg(p1 + H + j);
            const float gg = __ldcg(p0 + 2 * H + j) + __ldcg(p1 + 2 * H + j);
            const float go = __ldcg(p0 + 3 * H + j) + __ldcg(p1 + 3 * H + j);
            const float cn = sigf(gf) * g_d1c[i] + sigf(gi) * tanhf(gg);
            g_d1c[i] = cn;
            g_d1h[i] = sigf(go) * tanhf(cn);
        }
        gbar(phase);
    }

    // final logits for t = T-1
    if (cta >= 32 && cta < 48) {
        const int nt = cta - 32;
        ull acc[2][4] = {{0, 0, 0, 0}, {0, 0, 0, 0}};
        gcore<128, 32, true>(g_d1h, H, Wout + (size_t)nt * 32 * H, H, H, As, Bs, acc);
        store_tile<32>(acc, nullptr, 0, bout + nt * 32, nullptr,
                       out + (size_t)(T - 1) * V + nt * 32, T * V);
    }
}

// ---------------- host ----------------
static inline void* sym(const void* s)
{
    void* p = nullptr;
    cudaGetSymbolAddress(&p, s);
    return p;
}

extern "C" void kernel_launch(void* const* d_in, const int* in_sizes, int n_in,
                              void* d_out, int out_size)
{
    (void)in_sizes; (void)n_in; (void)out_size;

    const int*   src   = (const int*)  d_in[0];
    const int*   decin = (const int*)  d_in[1];
    const float* emb   = (const float*)d_in[2];
    const float* eWih0 = (const float*)d_in[3];
    const float* eWhh0 = (const float*)d_in[4];
    const float* ebih0 = (const float*)d_in[5];
    const float* ebhh0 = (const float*)d_in[6];
    const float* eWih1 = (const float*)d_in[7];
    const float* eWhh1 = (const float*)d_in[8];
    const float* ebih1 = (const float*)d_in[9];
    const float* ebhh1 = (const float*)d_in[10];
    const float* dWih0 = (const float*)d_in[11];
    const float* dWhh0 = (const float*)d_in[12];
    const float* dbih0 = (const float*)d_in[13];
    const float* dbhh0 = (const float*)d_in[14];
    const float* dWih1 = (const float*)d_in[15];
    const float* dWhh1 = (const float*)d_in[16];
    const float* dbih1 = (const float*)d_in[17];
    const float* dbhh1 = (const float*)d_in[18];
    const float* Wq    = (const float*)d_in[19];
    const float* bq    = (const float*)d_in[20];
    const float* Wout  = (const float*)d_in[21];
    const float* bout  = (const float*)d_in[22];
    float* out = (float*)d_out;

    float* xs   = (float*)sym(g_xs);
    float* pre  = (float*)sym(g_pre);
    float* y0   = (float*)sym(g_y0);
    float* enc  = (float*)sym(g_enc);
    float* edec = (float*)sym(g_edec);
    float* d0h  = (float*)sym(g_d0h);
    float* d0c  = (float*)sym(g_d0c);
    float* d1h  = (float*)sym(g_d1h);
    float* d1c  = (float*)sym(g_d1c);

    const long long SBG = (long long)S * B * G;

    // 1) source embedding (normal + time-reversed copies)
    {
        const long long n = (long long)S * B * E;
        embed_src_k<<<(unsigned)((n + 255) / 256), 256>>>(src, emb);
    }

    // 2) encoder layer 0 input projections (both dirs, biases folded)
    gemm2_k<<<dim3(G / 64, (S * B) / 64, 2), 256>>>(
        xs, E, E, eWih0, E, ebih0, ebhh0, pre, G,
        (long long)S * B * E, (long long)G * E, G, SBG);

    // 3) encoder layer 0 recurrence (persistent)
    enc_layer_k<<<NB, NT>>>(pre, eWhh0, y0, y0 + (size_t)S * B * H2, d0h, d0c);

    // 4) encoder layer 1 input projections
    gemm2_k<<<dim3(G / 64, (S * B) / 64, 2), 256>>>(
        y0, H2, H2, eWih1, H2, ebih1, ebhh1, pre, G,
        (long long)S * B * H2, (long long)G * H2, G, SBG);

    // 5) encoder layer 1 recurrence (persistent)
    enc_layer_k<<<NB, NT>>>(pre, eWhh1, enc, nullptr, d1h, d1c);

    // 6) decoder embedding + embedding projection (biases folded)
    {
        const long long n = (long long)T * B * E;
        embed_dec_k<<<(unsigned)((n + 255) / 256), 256>>>(decin, emb);
    }
    gemm2_k<<<dim3(G / 64, (T * B) / 64, 1), 256>>>(
        edec, E, E, dWih0, E + H2, dbih0, dbhh0, pre, G, 0, 0, 0, 0);

    // 7) decoder (persistent)
    dec_k<<<NB, NT>>>(pre, dWih0 + E, E + H2, dWhh0,
                      dWih1, dWhh1, dbih1, dbhh1,
                      Wq, bq, Wout, bout, src, enc, out);
}